// round 4
// baseline (speedup 1.0000x reference)
#include <cuda_runtime.h>
#include <cstdint>

typedef unsigned long long ull;

// ---------------------------------------------------------------------------
// Problem constants
// ---------------------------------------------------------------------------
constexpr int B_ = 16, S_ = 2048, D_ = 128;
constexpr int BQ = 128, BK = 128;
constexpr int QSTR = 132;           // Qs row stride (floats), even (LDS.64-able)
constexpr int KSTR = 130;           // Kt / P row stride, even
constexpr int NIT  = S_ / BK;       // 16

// Packed dropout keep-mask: 16*2048*2048 bits = 8 MB
__device__ __align__(16) unsigned int g_mask[(1u << 26) / 32];

// ---------------------------------------------------------------------------
// Threefry-2x32 (JAX partitionable): key=(0,42), ctr=(0,idx), draw = x0^x1
// ---------------------------------------------------------------------------
__device__ __forceinline__ void tf_round(unsigned &x0, unsigned &x1, int r) {
    x0 += x1;
    x1 = __funnelshift_l(x1, x1, r);
    x1 ^= x0;
}

__global__ void __launch_bounds__(256) mask_kernel(const float* __restrict__ p_dropout) {
    const unsigned idx = blockIdx.x * 256u + threadIdx.x;
    const unsigned ks0 = 0u, ks1 = 42u, ks2 = 0x1BD11BDAu ^ 42u;
    unsigned x0 = ks0, x1 = idx + ks1;
    tf_round(x0,x1,13); tf_round(x0,x1,15); tf_round(x0,x1,26); tf_round(x0,x1,6);
    x0 += ks1; x1 += ks2 + 1u;
    tf_round(x0,x1,17); tf_round(x0,x1,29); tf_round(x0,x1,16); tf_round(x0,x1,24);
    x0 += ks2; x1 += ks0 + 2u;
    tf_round(x0,x1,13); tf_round(x0,x1,15); tf_round(x0,x1,26); tf_round(x0,x1,6);
    x0 += ks0; x1 += ks1 + 3u;
    tf_round(x0,x1,17); tf_round(x0,x1,29); tf_round(x0,x1,16); tf_round(x0,x1,24);
    x0 += ks1; x1 += ks2 + 4u;
    tf_round(x0,x1,13); tf_round(x0,x1,15); tf_round(x0,x1,26); tf_round(x0,x1,6);
    x0 += ks2; x1 += ks0 + 5u;
    const unsigned bits = x0 ^ x1;
    const float kp = 1.0f - *p_dropout;
    const float u  = __uint_as_float((bits >> 9) | 0x3f800000u) - 1.0f;
    const unsigned ballot = __ballot_sync(0xffffffffu, u < kp);
    if ((threadIdx.x & 31u) == 0u) g_mask[idx >> 5] = ballot;
}

// ---------------------------------------------------------------------------
// Packed fp32 helpers (Blackwell f32x2 pipe)
// ---------------------------------------------------------------------------
__device__ __forceinline__ ull pack2(float lo, float hi) {
    ull r; asm("mov.b64 %0, {%1, %2};" : "=l"(r) : "f"(lo), "f"(hi)); return r;
}
__device__ __forceinline__ void unpack2(ull v, float &lo, float &hi) {
    asm("mov.b64 {%0, %1}, %2;" : "=f"(lo), "=f"(hi) : "l"(v));
}
__device__ __forceinline__ void ffma2(ull &acc, ull a, ull b) {
    asm("fma.rn.f32x2 %0, %1, %2, %0;" : "+l"(acc) : "l"(a), "l"(b));
}
__device__ __forceinline__ void fmul2(ull &d, ull a) {
    asm("mul.rn.f32x2 %0, %0, %1;" : "+l"(d) : "l"(a));
}

// logical col c -> physical slot: pair p of thread tx sits at p*32 + 2*tx (+e)
// inverse: phys p*32+2t+e  <->  logical c = t*8 + p*2 + e
__device__ __forceinline__ int permc(int c) {
    return ((c & 7) >> 1) * 32 + (c >> 3) * 2 + (c & 1);
}

// ---------------------------------------------------------------------------
// Flash attention, BQ=BK=128, 512 threads, 4x8 micro-tiles, f32x2 FMA.
// ---------------------------------------------------------------------------
__global__ void __launch_bounds__(512, 1) attn_kernel(
    const float* __restrict__ Q, const float* __restrict__ K,
    const float* __restrict__ V, const float* __restrict__ inv_scale,
    const float* __restrict__ p_dropout, float* __restrict__ Out)
{
    extern __shared__ float sm[];
    float* Qs = sm;                    // [128][QSTR]
    float* KP = Qs + 128 * QSTR;       // Kt [kk][KSTR] (perm) / P [row][KSTR] (perm)
    float* Vs = KP + 128 * KSTR;       // [128][128] perm cols
    float* rs = Vs + 128 * 128;        // [128]

    const int b     = blockIdx.y;
    const int qbase = blockIdx.x * BQ;
    const int tid   = threadIdx.x;
    const int tx    = tid & 15;        // 16 col groups (8 logical cols)
    const int ty    = tid >> 4;        // 32 row groups (4 rows)

    const float kp = 1.0f - *p_dropout;
    const float* Qb = Q + (size_t)(b * S_ + qbase) * D_;
    const float* Kb = K + (size_t)b * S_ * D_;
    const float* Vb = V + (size_t)b * S_ * D_;

    // ---- load Q tile (once) ----
    for (int t = tid; t < 128 * 32; t += 512) {
        const int r = t >> 5, c4 = (t & 31) << 2;
        *reinterpret_cast<float4*>(Qs + r * QSTR + c4) =
            *reinterpret_cast<const float4*>(Qb + r * D_ + c4);
    }
    if (tid < 128) rs[tid] = 1.0f / inv_scale[(size_t)b * S_ + qbase + tid];

    ull O2[4][4];
    float mrun[4], Zrun[4];
#pragma unroll
    for (int i = 0; i < 4; i++) {
        mrun[i] = -1e30f; Zrun[i] = 0.0f;
#pragma unroll
        for (int v = 0; v < 4; v++) O2[i][v] = 0ull;
    }

    unsigned wbase[4];
#pragma unroll
    for (int i = 0; i < 4; i++)
        wbase[i] = (unsigned)(b * S_ + qbase + 4 * ty + i) * (S_ / 32);
    const unsigned wword  = (unsigned)(tx >> 2);
    const unsigned wshift = (unsigned)(8 * (tx & 3));

    for (int kb = 0; kb < NIT; kb++) {
        __syncthreads();   // prev PV done: KP and Vs reusable

        // ---- load K transposed+permuted, V permuted ----
        const float* Kt = Kb + (size_t)kb * BK * D_;
        const float* Vt = Vb + (size_t)kb * BK * D_;
        for (int t = tid; t < 128 * 32; t += 512) {
            const int r = t >> 5, c4 = (t & 31) << 2;
            const float4 k4 = *reinterpret_cast<const float4*>(Kt + r * D_ + c4);
            const int pc = permc(r);
            KP[(c4 + 0) * KSTR + pc] = k4.x;
            KP[(c4 + 1) * KSTR + pc] = k4.y;
            KP[(c4 + 2) * KSTR + pc] = k4.z;
            KP[(c4 + 3) * KSTR + pc] = k4.w;
            const float4 v4 = *reinterpret_cast<const float4*>(Vt + r * D_ + c4);
            float* vr = Vs + r * 128;
            vr[permc(c4 + 0)] = v4.x;
            vr[permc(c4 + 1)] = v4.y;
            vr[permc(c4 + 2)] = v4.z;
            vr[permc(c4 + 3)] = v4.w;
        }
        __syncthreads();

        // ---- QK: acc[4 rows][4 col-pairs], kk unrolled by 2 ----
        ull acc[4][4];
#pragma unroll
        for (int i = 0; i < 4; i++)
#pragma unroll
            for (int p = 0; p < 4; p++) acc[i][p] = 0ull;

        const float* qp = Qs + 4 * ty * QSTR;
        const float* kr = KP + 2 * tx;
#pragma unroll 4
        for (int kk = 0; kk < 128; kk += 2) {
            const float* k0 = kr + kk * KSTR;
            const float* k1 = k0 + KSTR;
            const ull b00 = *reinterpret_cast<const ull*>(k0);
            const ull b01 = *reinterpret_cast<const ull*>(k0 + 32);
            const ull b02 = *reinterpret_cast<const ull*>(k0 + 64);
            const ull b03 = *reinterpret_cast<const ull*>(k0 + 96);
            const ull b10 = *reinterpret_cast<const ull*>(k1);
            const ull b11 = *reinterpret_cast<const ull*>(k1 + 32);
            const ull b12 = *reinterpret_cast<const ull*>(k1 + 64);
            const ull b13 = *reinterpret_cast<const ull*>(k1 + 96);
#pragma unroll
            for (int i = 0; i < 4; i++) {
                const ull q2 = *reinterpret_cast<const ull*>(qp + i * QSTR + kk);
                float qa, qb; unpack2(q2, qa, qb);
                const ull a0 = pack2(qa, qa);
                const ull a1 = pack2(qb, qb);
                ffma2(acc[i][0], a0, b00); ffma2(acc[i][1], a0, b01);
                ffma2(acc[i][2], a0, b02); ffma2(acc[i][3], a0, b03);
                ffma2(acc[i][0], a1, b10); ffma2(acc[i][1], a1, b11);
                ffma2(acc[i][2], a1, b12); ffma2(acc[i][3], a1, b13);
            }
        }
        __syncthreads();   // K reads done -> KP reusable as P

        // ---- softmax + dropout + write P (permuted cols) ----
        const unsigned woff = (unsigned)(kb * 4) + wword;
#pragma unroll
        for (int i = 0; i < 4; i++) {
            float s[8];
            unpack2(acc[i][0], s[0], s[1]);
            unpack2(acc[i][1], s[2], s[3]);
            unpack2(acc[i][2], s[4], s[5]);
            unpack2(acc[i][3], s[6], s[7]);
            const float rsc = rs[4 * ty + i];
#pragma unroll
            for (int j = 0; j < 8; j++) s[j] *= rsc;

            float mx = fmaxf(fmaxf(fmaxf(s[0], s[1]), fmaxf(s[2], s[3])),
                             fmaxf(fmaxf(s[4], s[5]), fmaxf(s[6], s[7])));
            mx = fmaxf(mx, __shfl_xor_sync(0xffffffffu, mx, 1));
            mx = fmaxf(mx, __shfl_xor_sync(0xffffffffu, mx, 2));
            mx = fmaxf(mx, __shfl_xor_sync(0xffffffffu, mx, 4));
            mx = fmaxf(mx, __shfl_xor_sync(0xffffffffu, mx, 8));

            const float mn    = fmaxf(mrun[i], mx);
            const float alpha = __expf(mrun[i] - mn);
            mrun[i] = mn;

            float p[8];
#pragma unroll
            for (int j = 0; j < 8; j++) p[j] = __expf(s[j] - mn);
            float rsum = ((p[0] + p[1]) + (p[2] + p[3])) + ((p[4] + p[5]) + (p[6] + p[7]));
            rsum += __shfl_xor_sync(0xffffffffu, rsum, 1);
            rsum += __shfl_xor_sync(0xffffffffu, rsum, 2);
            rsum += __shfl_xor_sync(0xffffffffu, rsum, 4);
            rsum += __shfl_xor_sync(0xffffffffu, rsum, 8);
            Zrun[i] = Zrun[i] * alpha + rsum;

            const ull al2 = pack2(alpha, alpha);
#pragma unroll
            for (int v = 0; v < 4; v++) fmul2(O2[i][v], al2);

            const unsigned mw = g_mask[wbase[i] + woff];
            const unsigned mb = (mw >> wshift) & 0xffu;
#pragma unroll
            for (int j = 0; j < 8; j++)
                if (!((mb >> j) & 1u)) p[j] = 0.0f;

            float* prow = KP + (4 * ty + i) * KSTR + 2 * tx;
            *reinterpret_cast<ull*>(prow)      = pack2(p[0], p[1]);
            *reinterpret_cast<ull*>(prow + 32) = pack2(p[2], p[3]);
            *reinterpret_cast<ull*>(prow + 64) = pack2(p[4], p[5]);
            *reinterpret_cast<ull*>(prow + 96) = pack2(p[6], p[7]);
        }
        __syncthreads();

        // ---- PV: O2 += P * V ----
        const float* pvP = KP + 4 * ty * KSTR;
#pragma unroll
        for (int pp = 0; pp < 4; pp++) {
#pragma unroll 4
            for (int t = 0; t < 16; t++) {
                const int ph = pp * 32 + t * 2;   // P physical pair offset
                const int c0 = t * 8 + pp * 2;    // logical key rows c0, c0+1
                const float* v0 = Vs + c0 * 128 + 2 * tx;
                const float* v1 = v0 + 128;
                ull vb0[4], vb1[4];
#pragma unroll
                for (int v = 0; v < 4; v++) {
                    vb0[v] = *reinterpret_cast<const ull*>(v0 + v * 32);
                    vb1[v] = *reinterpret_cast<const ull*>(v1 + v * 32);
                }
#pragma unroll
                for (int i = 0; i < 4; i++) {
                    const ull pp2 = *reinterpret_cast<const ull*>(pvP + i * KSTR + ph);
                    float f0, f1; unpack2(pp2, f0, f1);
                    const ull d0 = pack2(f0, f0), d1 = pack2(f1, f1);
                    ffma2(O2[i][0], d0, vb0[0]); ffma2(O2[i][1], d0, vb0[1]);
                    ffma2(O2[i][2], d0, vb0[2]); ffma2(O2[i][3], d0, vb0[3]);
                    ffma2(O2[i][0], d1, vb1[0]); ffma2(O2[i][1], d1, vb1[1]);
                    ffma2(O2[i][2], d1, vb1[2]); ffma2(O2[i][3], d1, vb1[3]);
                }
            }
        }
    }

    // ---- epilogue: out = O / (Z * keep_prob); logical col = 8tx + 2v + e ----
#pragma unroll
    for (int i = 0; i < 4; i++) {
        const float inv = 1.0f / (Zrun[i] * kp);
        float o[8];
        unpack2(O2[i][0], o[0], o[1]);
        unpack2(O2[i][1], o[2], o[3]);
        unpack2(O2[i][2], o[4], o[5]);
        unpack2(O2[i][3], o[6], o[7]);
        float* orow = Out + (size_t)(b * S_ + qbase + 4 * ty + i) * D_ + 8 * tx;
        *reinterpret_cast<float4*>(orow) =
            make_float4(o[0] * inv, o[1] * inv, o[2] * inv, o[3] * inv);
        *reinterpret_cast<float4*>(orow + 4) =
            make_float4(o[4] * inv, o[5] * inv, o[6] * inv, o[7] * inv);
    }
}

// ---------------------------------------------------------------------------
// Launch
// ---------------------------------------------------------------------------
extern "C" void kernel_launch(void* const* d_in, const int* in_sizes, int n_in,
                              void* d_out, int out_size) {
    const float* Q   = (const float*)d_in[0];
    const float* K   = (const float*)d_in[1];
    const float* V   = (const float*)d_in[2];
    const float* isf = (const float*)d_in[3];
    const float* dp  = (const float*)d_in[4];
    float* Out = (float*)d_out;

    constexpr int SMEM_BYTES =
        (128 * QSTR + 128 * KSTR + 128 * 128 + 128) * (int)sizeof(float);
    cudaFuncSetAttribute(attn_kernel,
                         cudaFuncAttributeMaxDynamicSharedMemorySize, SMEM_BYTES);

    mask_kernel<<<(1u << 26) / 256, 256>>>(dp);

    dim3 grid(S_ / BQ, B_);
    attn_kernel<<<grid, 512, SMEM_BYTES>>>(Q, K, V, isf, dp, Out);
}

// round 6
// speedup vs baseline: 2.0388x; 2.0388x over previous
#include <cuda_runtime.h>
#include <cuda_fp16.h>
#include <cstdint>

typedef unsigned long long ull;
typedef unsigned uint;

// ---------------------------------------------------------------------------
// Problem constants
// ---------------------------------------------------------------------------
constexpr int B_ = 16, S_ = 2048, D_ = 128;
constexpr int BQ = 128, BK = 128;
constexpr int NIT = S_ / BK;        // 16
constexpr int HSTR = 136;           // halfs per smem row (272B, 16B aligned rows)

// smem byte offsets: six fp16 planes [128][HSTR]
constexpr int PLANE = 128 * HSTR * 2;   // 34816
constexpr int QHI = 0;
constexpr int QLO = QHI + PLANE;
constexpr int KHI = QLO + PLANE;
constexpr int KLO = KHI + PLANE;
constexpr int VHI = KLO + PLANE;
constexpr int VLO = VHI + PLANE;
constexpr int SMEM_BYTES = VLO + PLANE;   // 208896

// Packed dropout keep-mask: 16*2048*2048 bits = 8 MB
__device__ __align__(16) unsigned int g_mask[(1u << 26) / 32];

// ---------------------------------------------------------------------------
// Threefry-2x32 (JAX partitionable): key=(0,42), ctr=(0,idx), draw = x0^x1
// ---------------------------------------------------------------------------
__device__ __forceinline__ void tf_round(unsigned &x0, unsigned &x1, int r) {
    x0 += x1;
    x1 = __funnelshift_l(x1, x1, r);
    x1 ^= x0;
}

__global__ void __launch_bounds__(256) mask_kernel(const float* __restrict__ p_dropout) {
    const unsigned idx = blockIdx.x * 256u + threadIdx.x;
    const unsigned ks0 = 0u, ks1 = 42u, ks2 = 0x1BD11BDAu ^ 42u;
    unsigned x0 = ks0, x1 = idx + ks1;
    tf_round(x0,x1,13); tf_round(x0,x1,15); tf_round(x0,x1,26); tf_round(x0,x1,6);
    x0 += ks1; x1 += ks2 + 1u;
    tf_round(x0,x1,17); tf_round(x0,x1,29); tf_round(x0,x1,16); tf_round(x0,x1,24);
    x0 += ks2; x1 += ks0 + 2u;
    tf_round(x0,x1,13); tf_round(x0,x1,15); tf_round(x0,x1,26); tf_round(x0,x1,6);
    x0 += ks0; x1 += ks1 + 3u;
    tf_round(x0,x1,17); tf_round(x0,x1,29); tf_round(x0,x1,16); tf_round(x0,x1,24);
    x0 += ks1; x1 += ks2 + 4u;
    tf_round(x0,x1,13); tf_round(x0,x1,15); tf_round(x0,x1,26); tf_round(x0,x1,6);
    x0 += ks2; x1 += ks0 + 5u;
    const unsigned bits = x0 ^ x1;
    const float kp = 1.0f - *p_dropout;
    const float u  = __uint_as_float((bits >> 9) | 0x3f800000u) - 1.0f;
    const unsigned ballot = __ballot_sync(0xffffffffu, u < kp);
    if ((threadIdx.x & 31u) == 0u) g_mask[idx >> 5] = ballot;
}

// ---------------------------------------------------------------------------
// mma / ldmatrix helpers (baseline PTX, sm_80+ — legal on compute_103)
// ---------------------------------------------------------------------------
__device__ __forceinline__ unsigned smem_u32(const void* p) {
    unsigned a;
    asm("{ .reg .u64 t; cvta.to.shared.u64 t, %1; cvt.u32.u64 %0, t; }"
        : "=r"(a) : "l"(p));
    return a;
}

__device__ __forceinline__ void mma16816(float* c, const uint* a, uint b0, uint b1) {
    asm volatile(
        "mma.sync.aligned.m16n8k16.row.col.f32.f16.f16.f32 "
        "{%0,%1,%2,%3}, {%4,%5,%6,%7}, {%8,%9}, {%0,%1,%2,%3};"
        : "+f"(c[0]), "+f"(c[1]), "+f"(c[2]), "+f"(c[3])
        : "r"(a[0]), "r"(a[1]), "r"(a[2]), "r"(a[3]), "r"(b0), "r"(b1));
}

__device__ __forceinline__ void ldsm4(uint* r, uint addr) {
    asm volatile("ldmatrix.sync.aligned.m8n8.x4.shared.b16 {%0,%1,%2,%3}, [%4];"
        : "=r"(r[0]), "=r"(r[1]), "=r"(r[2]), "=r"(r[3]) : "r"(addr));
}
__device__ __forceinline__ void ldsm4t(uint* r, uint addr) {
    asm volatile("ldmatrix.sync.aligned.m8n8.x4.trans.shared.b16 {%0,%1,%2,%3}, [%4];"
        : "=r"(r[0]), "=r"(r[1]), "=r"(r[2]), "=r"(r[3]) : "r"(addr));
}

__device__ __forceinline__ float hif(float x) {           // round-trip to fp16
    return __half2float(__float2half_rn(x));
}
__device__ __forceinline__ uint packh2(float lo, float hi) {  // {f16(lo), f16(hi)}
    uint r; asm("cvt.rn.f16x2.f32 %0, %1, %2;" : "=r"(r) : "f"(hi), "f"(lo)); return r;
}

// convert float4 -> hi/lo fp16 pairs and store 8B each to two planes
__device__ __forceinline__ void split_store(char* smp, int hi_off, int lo_off,
                                            int byte_off, float4 v) {
    const float h0 = hif(v.x), h1 = hif(v.y), h2 = hif(v.z), h3 = hif(v.w);
    const uint hi01 = packh2(h0, h1), hi23 = packh2(h2, h3);
    const uint lo01 = packh2(v.x - h0, v.y - h1), lo23 = packh2(v.z - h2, v.w - h3);
    *reinterpret_cast<ull*>(smp + hi_off + byte_off) = (ull)hi01 | ((ull)hi23 << 32);
    *reinterpret_cast<ull*>(smp + lo_off + byte_off) = (ull)lo01 | ((ull)lo23 << 32);
}

// ---------------------------------------------------------------------------
// Flash attention: split-fp16 HMMA, BQ=BK=128, 256 threads, warp-owned rows.
// ---------------------------------------------------------------------------
__global__ void __launch_bounds__(256, 1) attn_kernel(
    const float* __restrict__ Q, const float* __restrict__ K,
    const float* __restrict__ V, const float* __restrict__ inv_scale,
    const float* __restrict__ p_dropout, float* __restrict__ Out)
{
    extern __shared__ char smp[];
    const uint sb = smem_u32(smp);

    const int b     = blockIdx.y;
    const int qbase = blockIdx.x * BQ;
    const int tid   = threadIdx.x;
    const int lane  = tid & 31;
    const int warp  = tid >> 5;
    const int qr    = warp * 16;        // warp's 16 query rows
    const int g     = lane >> 2;        // row group 0..7
    const int tc    = lane & 3;         // col group

    const float kp = 1.0f - *p_dropout;
    const float* Qb = Q + (size_t)(b * S_ + qbase) * D_;
    const float* Kb = K + (size_t)b * S_ * D_;
    const float* Vb = V + (size_t)b * S_ * D_;

    // ---- Q -> hi/lo fp16 planes (once) ----
    for (int t = tid; t < 128 * 32; t += 256) {
        const int r = t >> 5, c4 = (t & 31) << 2;
        split_store(smp, QHI, QLO, (r * HSTR + c4) * 2,
                    *reinterpret_cast<const float4*>(Qb + r * D_ + c4));
    }

    const float rsc0 = 1.0f / inv_scale[(size_t)b * S_ + qbase + qr + g];
    const float rsc1 = 1.0f / inv_scale[(size_t)b * S_ + qbase + qr + g + 8];

    float oacc[16][4];
#pragma unroll
    for (int nt = 0; nt < 16; nt++)
#pragma unroll
        for (int j = 0; j < 4; j++) oacc[nt][j] = 0.0f;
    float m0 = -1e30f, m1 = -1e30f, z0 = 0.0f, z1 = 0.0f;

    const unsigned rowb0 = (unsigned)(b * S_ + qbase + qr + g) * 64u;
    const unsigned rowb1 = rowb0 + 512u;   // +8 rows * 64 words

    // per-lane ldmatrix byte offsets
    const uint aoff = (uint)((qr + (lane & 15)) * HSTR + ((lane >> 4) << 3)) * 2;
    const uint boff = (uint)((((lane >> 4) << 3) + (lane & 7)) * HSTR
                             + (((lane >> 3) & 1) << 3)) * 2;
    const uint voff = (uint)(((((lane >> 3) & 1) << 3) + (lane & 7)) * HSTR
                             + ((lane >> 4) << 3)) * 2;

    for (int kb = 0; kb < NIT; kb++) {
        __syncthreads();   // previous PV reads of V done

        // ---- load K,V tile -> hi/lo fp16 planes ----
        const float* Kt = Kb + (size_t)kb * BK * D_;
        const float* Vt = Vb + (size_t)kb * BK * D_;
        for (int t = tid; t < 128 * 32; t += 256) {
            const int r = t >> 5, c4 = (t & 31) << 2;
            const int off = (r * HSTR + c4) * 2;
            split_store(smp, KHI, KLO, off,
                        *reinterpret_cast<const float4*>(Kt + r * D_ + c4));
            split_store(smp, VHI, VLO, off,
                        *reinterpret_cast<const float4*>(Vt + r * D_ + c4));
        }
        __syncthreads();

        // ---- S = Q K^T : 16 n-tiles x 4 f32 per thread ----
        float sacc[16][4];
#pragma unroll
        for (int nt = 0; nt < 16; nt++)
#pragma unroll
            for (int j = 0; j < 4; j++) sacc[nt][j] = 0.0f;

#pragma unroll
        for (int ks = 0; ks < 8; ks++) {
            uint ah[4], al[4];
            ldsm4(ah, sb + QHI + aoff + ks * 32);
            ldsm4(al, sb + QLO + aoff + ks * 32);
#pragma unroll
            for (int nt2 = 0; nt2 < 8; nt2++) {
                uint bh[4], bl[4];
                const uint kbo = boff + (uint)(nt2 * 16 * HSTR * 2 + ks * 32);
                ldsm4(bh, sb + KHI + kbo);
                ldsm4(bl, sb + KLO + kbo);
                mma16816(sacc[2 * nt2],     ah, bh[0], bh[1]);
                mma16816(sacc[2 * nt2],     al, bh[0], bh[1]);
                mma16816(sacc[2 * nt2],     ah, bl[0], bl[1]);
                mma16816(sacc[2 * nt2 + 1], ah, bh[2], bh[3]);
                mma16816(sacc[2 * nt2 + 1], al, bh[2], bh[3]);
                mma16816(sacc[2 * nt2 + 1], ah, bl[2], bl[3]);
            }
        }

        // ---- scale + online softmax (rows g, g+8; reduce over 4-lane group) ----
        float mx0 = -1e30f, mx1 = -1e30f;
#pragma unroll
        for (int nt = 0; nt < 16; nt++) {
            sacc[nt][0] *= rsc0; sacc[nt][1] *= rsc0;
            sacc[nt][2] *= rsc1; sacc[nt][3] *= rsc1;
            mx0 = fmaxf(mx0, fmaxf(sacc[nt][0], sacc[nt][1]));
            mx1 = fmaxf(mx1, fmaxf(sacc[nt][2], sacc[nt][3]));
        }
        mx0 = fmaxf(mx0, __shfl_xor_sync(0xffffffffu, mx0, 1));
        mx0 = fmaxf(mx0, __shfl_xor_sync(0xffffffffu, mx0, 2));
        mx1 = fmaxf(mx1, __shfl_xor_sync(0xffffffffu, mx1, 1));
        mx1 = fmaxf(mx1, __shfl_xor_sync(0xffffffffu, mx1, 2));

        const float mn0 = fmaxf(m0, mx0), mn1 = fmaxf(m1, mx1);
        const float al0 = __expf(m0 - mn0), al1 = __expf(m1 - mn1);
        m0 = mn0; m1 = mn1;

        float zp0 = 0.0f, zp1 = 0.0f;
#pragma unroll
        for (int nt = 0; nt < 16; nt++) {
            sacc[nt][0] = __expf(sacc[nt][0] - mn0); zp0 += sacc[nt][0];
            sacc[nt][1] = __expf(sacc[nt][1] - mn0); zp0 += sacc[nt][1];
            sacc[nt][2] = __expf(sacc[nt][2] - mn1); zp1 += sacc[nt][2];
            sacc[nt][3] = __expf(sacc[nt][3] - mn1); zp1 += sacc[nt][3];
        }
        z0 = z0 * al0 + zp0;
        z1 = z1 * al1 + zp1;

#pragma unroll
        for (int nt = 0; nt < 16; nt++) {
            oacc[nt][0] *= al0; oacc[nt][1] *= al0;
            oacc[nt][2] *= al1; oacc[nt][3] *= al1;
        }

        // ---- dropout mask on P ----
        uint w0[4], w1[4];
#pragma unroll
        for (int j = 0; j < 4; j++) {
            w0[j] = g_mask[rowb0 + (unsigned)(kb * 4 + j)];
            w1[j] = g_mask[rowb1 + (unsigned)(kb * 4 + j)];
        }
#pragma unroll
        for (int nt = 0; nt < 16; nt++) {
            const uint bit = (uint)((nt & 3) * 8 + tc * 2);
            const uint ww0 = w0[nt >> 2], ww1 = w1[nt >> 2];
            if (!((ww0 >> bit) & 1u))        sacc[nt][0] = 0.0f;
            if (!((ww0 >> (bit + 1)) & 1u))  sacc[nt][1] = 0.0f;
            if (!((ww1 >> bit) & 1u))        sacc[nt][2] = 0.0f;
            if (!((ww1 >> (bit + 1)) & 1u))  sacc[nt][3] = 0.0f;
        }

        // ---- O += P V : repack P fragments, V via ldmatrix.trans ----
#pragma unroll
        for (int ks = 0; ks < 8; ks++) {
            const float* sA = sacc[2 * ks];
            const float* sB = sacc[2 * ks + 1];
            const float hA0 = hif(sA[0]), hA1 = hif(sA[1]);
            const float hA2 = hif(sA[2]), hA3 = hif(sA[3]);
            const float hB0 = hif(sB[0]), hB1 = hif(sB[1]);
            const float hB2 = hif(sB[2]), hB3 = hif(sB[3]);
            uint ph[4], pl[4];
            ph[0] = packh2(hA0, hA1);           ph[1] = packh2(hA2, hA3);
            ph[2] = packh2(hB0, hB1);           ph[3] = packh2(hB2, hB3);
            pl[0] = packh2(sA[0] - hA0, sA[1] - hA1);
            pl[1] = packh2(sA[2] - hA2, sA[3] - hA3);
            pl[2] = packh2(sB[0] - hB0, sB[1] - hB1);
            pl[3] = packh2(sB[2] - hB2, sB[3] - hB3);

#pragma unroll
            for (int dt2 = 0; dt2 < 8; dt2++) {
                uint vh[4], vl[4];
                const uint vbo = voff + (uint)(ks * 16 * HSTR * 2 + dt2 * 32);
                ldsm4t(vh, sb + VHI + vbo);
                ldsm4t(vl, sb + VLO + vbo);
                mma16816(oacc[2 * dt2],     ph, vh[0], vh[1]);
                mma16816(oacc[2 * dt2],     pl, vh[0], vh[1]);
                mma16816(oacc[2 * dt2],     ph, vl[0], vl[1]);
                mma16816(oacc[2 * dt2 + 1], ph, vh[2], vh[3]);
                mma16816(oacc[2 * dt2 + 1], pl, vh[2], vh[3]);
                mma16816(oacc[2 * dt2 + 1], ph, vl[2], vl[3]);
            }
        }
    }

    // ---- epilogue: reduce Z across the 4-lane group, normalize, store ----
    z0 += __shfl_xor_sync(0xffffffffu, z0, 1);
    z0 += __shfl_xor_sync(0xffffffffu, z0, 2);
    z1 += __shfl_xor_sync(0xffffffffu, z1, 1);
    z1 += __shfl_xor_sync(0xffffffffu, z1, 2);
    const float inv0 = 1.0f / (z0 * kp);
    const float inv1 = 1.0f / (z1 * kp);

    float* o0 = Out + (size_t)(b * S_ + qbase + qr + g) * D_ + tc * 2;
    float* o1 = Out + (size_t)(b * S_ + qbase + qr + g + 8) * D_ + tc * 2;
#pragma unroll
    for (int nt = 0; nt < 16; nt++) {
        *reinterpret_cast<float2*>(o0 + nt * 8) =
            make_float2(oacc[nt][0] * inv0, oacc[nt][1] * inv0);
        *reinterpret_cast<float2*>(o1 + nt * 8) =
            make_float2(oacc[nt][2] * inv1, oacc[nt][3] * inv1);
    }
}

// ---------------------------------------------------------------------------
// Launch
// ---------------------------------------------------------------------------
extern "C" void kernel_launch(void* const* d_in, const int* in_sizes, int n_in,
                              void* d_out, int out_size) {
    const float* Q   = (const float*)d_in[0];
    const float* K   = (const float*)d_in[1];
    const float* V   = (const float*)d_in[2];
    const float* isf = (const float*)d_in[3];
    const float* dp  = (const float*)d_in[4];
    float* Out = (float*)d_out;

    cudaFuncSetAttribute(attn_kernel,
                         cudaFuncAttributeMaxDynamicSharedMemorySize, SMEM_BYTES);

    mask_kernel<<<(1u << 26) / 256, 256>>>(dp);

    dim3 grid(S_ / BQ, B_);
    attn_kernel<<<grid, 256, SMEM_BYTES>>>(Q, K, V, isf, dp, Out);
}

// round 7
// speedup vs baseline: 2.0739x; 1.0172x over previous
#include <cuda_runtime.h>
#include <cuda_fp16.h>
#include <cstdint>

typedef unsigned long long ull;
typedef unsigned uint;

// ---------------------------------------------------------------------------
// Problem constants
// ---------------------------------------------------------------------------
constexpr int B_ = 16, S_ = 2048, D_ = 128;
constexpr int BQ = 128, BK = 128;
constexpr int NIT = S_ / BK;        // 16
constexpr int HSTR = 136;           // halfs per smem row (272B)

constexpr int PLANE = 128 * HSTR * 2;   // 34816 B
constexpr int QHI = 0;
constexpr int QLO = QHI + PLANE;
constexpr int KHI = QLO + PLANE;    // P_hi overlays after QK
constexpr int KLO = KHI + PLANE;    // P_lo overlays
constexpr int VHI = KLO + PLANE;
constexpr int VLO = VHI + PLANE;
constexpr int REDM = VLO + PLANE;   // float[2][128]
constexpr int REDZ = REDM + 1024;   // float[2][128]
constexpr int SMEM_BYTES = REDZ + 1024;   // 210944

// Packed dropout keep-mask: 16*2048*2048 bits = 8 MB
__device__ __align__(16) unsigned int g_mask[(1u << 26) / 32];

// ---------------------------------------------------------------------------
// Threefry-2x32 (JAX partitionable): key=(0,42), ctr=(0,idx), draw = x0^x1
// ---------------------------------------------------------------------------
__device__ __forceinline__ void tf_round(unsigned &x0, unsigned &x1, int r) {
    x0 += x1;
    x1 = __funnelshift_l(x1, x1, r);
    x1 ^= x0;
}

__global__ void __launch_bounds__(256) mask_kernel(const float* __restrict__ p_dropout) {
    const unsigned idx = blockIdx.x * 256u + threadIdx.x;
    const unsigned ks0 = 0u, ks1 = 42u, ks2 = 0x1BD11BDAu ^ 42u;
    unsigned x0 = ks0, x1 = idx + ks1;
    tf_round(x0,x1,13); tf_round(x0,x1,15); tf_round(x0,x1,26); tf_round(x0,x1,6);
    x0 += ks1; x1 += ks2 + 1u;
    tf_round(x0,x1,17); tf_round(x0,x1,29); tf_round(x0,x1,16); tf_round(x0,x1,24);
    x0 += ks2; x1 += ks0 + 2u;
    tf_round(x0,x1,13); tf_round(x0,x1,15); tf_round(x0,x1,26); tf_round(x0,x1,6);
    x0 += ks0; x1 += ks1 + 3u;
    tf_round(x0,x1,17); tf_round(x0,x1,29); tf_round(x0,x1,16); tf_round(x0,x1,24);
    x0 += ks1; x1 += ks2 + 4u;
    tf_round(x0,x1,13); tf_round(x0,x1,15); tf_round(x0,x1,26); tf_round(x0,x1,6);
    x0 += ks2; x1 += ks0 + 5u;
    const unsigned bits = x0 ^ x1;
    const float kp = 1.0f - *p_dropout;
    const float u  = __uint_as_float((bits >> 9) | 0x3f800000u) - 1.0f;
    const unsigned ballot = __ballot_sync(0xffffffffu, u < kp);
    if ((threadIdx.x & 31u) == 0u) g_mask[idx >> 5] = ballot;
}

// ---------------------------------------------------------------------------
// mma / ldmatrix helpers (baseline PTX)
// ---------------------------------------------------------------------------
__device__ __forceinline__ unsigned smem_u32(const void* p) {
    unsigned a;
    asm("{ .reg .u64 t; cvta.to.shared.u64 t, %1; cvt.u32.u64 %0, t; }"
        : "=r"(a) : "l"(p));
    return a;
}

__device__ __forceinline__ void mma16816(float* c, const uint* a, uint b0, uint b1) {
    asm volatile(
        "mma.sync.aligned.m16n8k16.row.col.f32.f16.f16.f32 "
        "{%0,%1,%2,%3}, {%4,%5,%6,%7}, {%8,%9}, {%0,%1,%2,%3};"
        : "+f"(c[0]), "+f"(c[1]), "+f"(c[2]), "+f"(c[3])
        : "r"(a[0]), "r"(a[1]), "r"(a[2]), "r"(a[3]), "r"(b0), "r"(b1));
}

__device__ __forceinline__ void ldsm4(uint* r, uint addr) {
    asm volatile("ldmatrix.sync.aligned.m8n8.x4.shared.b16 {%0,%1,%2,%3}, [%4];"
        : "=r"(r[0]), "=r"(r[1]), "=r"(r[2]), "=r"(r[3]) : "r"(addr));
}
__device__ __forceinline__ void ldsm4t(uint* r, uint addr) {
    asm volatile("ldmatrix.sync.aligned.m8n8.x4.trans.shared.b16 {%0,%1,%2,%3}, [%4];"
        : "=r"(r[0]), "=r"(r[1]), "=r"(r[2]), "=r"(r[3]) : "r"(addr));
}

__device__ __forceinline__ float hif(float x) {
    return __half2float(__float2half_rn(x));
}
__device__ __forceinline__ uint packh2(float lo, float hi) {
    uint r; asm("cvt.rn.f16x2.f32 %0, %1, %2;" : "=r"(r) : "f"(hi), "f"(lo)); return r;
}

__device__ __forceinline__ void split_store(char* smp, int hi_off, int lo_off,
                                            int byte_off, float4 v) {
    const float h0 = hif(v.x), h1 = hif(v.y), h2 = hif(v.z), h3 = hif(v.w);
    const uint hi01 = packh2(h0, h1), hi23 = packh2(h2, h3);
    const uint lo01 = packh2(v.x - h0, v.y - h1), lo23 = packh2(v.z - h2, v.w - h3);
    *reinterpret_cast<ull*>(smp + hi_off + byte_off) = (ull)hi01 | ((ull)hi23 << 32);
    *reinterpret_cast<ull*>(smp + lo_off + byte_off) = (ull)lo01 | ((ull)lo23 << 32);
}

// ---------------------------------------------------------------------------
// Flash attention: split-fp16 HMMA, BQ=BK=128, 512 threads (16 warps).
// warp w: wq = w&7 -> q-rows 16*wq;  h = w>>3 -> key-half (QK) / d-half (PV).
// ---------------------------------------------------------------------------
__global__ void __launch_bounds__(512, 1) attn_kernel(
    const float* __restrict__ Q, const float* __restrict__ K,
    const float* __restrict__ V, const float* __restrict__ inv_scale,
    const float* __restrict__ p_dropout, float* __restrict__ Out)
{
    extern __shared__ char smp[];
    const uint sb = smem_u32(smp);

    const int b     = blockIdx.y;
    const int qbase = blockIdx.x * BQ;
    const int tid   = threadIdx.x;
    const int lane  = tid & 31;
    const int warp  = tid >> 5;
    const int wq    = warp & 7;
    const int h     = warp >> 3;
    const int qr    = wq * 16;
    const int g     = lane >> 2;
    const int tc    = lane & 3;

    const float kp = 1.0f - *p_dropout;
    const float* Qb = Q + (size_t)(b * S_ + qbase) * D_;
    const float* Kb = K + (size_t)b * S_ * D_;
    const float* Vb = V + (size_t)b * S_ * D_;

    float* redM = (float*)(smp + REDM);
    float* redZ = (float*)(smp + REDZ);

    // ---- Q -> hi/lo fp16 planes (once) ----
    for (int t = tid; t < 128 * 32; t += 512) {
        const int r = t >> 5, c4 = (t & 31) << 2;
        split_store(smp, QHI, QLO, (r * HSTR + c4) * 2,
                    *reinterpret_cast<const float4*>(Qb + r * D_ + c4));
    }

    const float rsc0 = 1.0f / inv_scale[(size_t)b * S_ + qbase + qr + g];
    const float rsc1 = 1.0f / inv_scale[(size_t)b * S_ + qbase + qr + g + 8];

    float oacc[8][4];
#pragma unroll
    for (int nt = 0; nt < 8; nt++)
#pragma unroll
        for (int j = 0; j < 4; j++) oacc[nt][j] = 0.0f;
    float m0 = -1e30f, m1 = -1e30f, z0 = 0.0f, z1 = 0.0f;

    const unsigned rowb0 = (unsigned)(b * S_ + qbase + qr + g) * 64u;
    const unsigned rowb1 = rowb0 + 512u;

    // per-lane ldmatrix byte offsets
    const uint aoff = (uint)((qr + (lane & 15)) * HSTR + ((lane >> 4) << 3)) * 2;
    const uint boff = (uint)(((h * 64 + ((lane >> 4) << 3)) + (lane & 7)) * HSTR
                             + (((lane >> 3) & 1) << 3)) * 2;
    const uint voff = (uint)(((((lane >> 3) & 1) << 3) + (lane & 7)) * HSTR
                             + (h * 64 + ((lane >> 4) << 3))) * 2;

    for (int kb = 0; kb < NIT; kb++) {
        __syncthreads();   // (a) prior PV reads of P/V done

        // ---- load K,V tile -> hi/lo fp16 planes (K planes also serve as P) ----
        const float* Kt = Kb + (size_t)kb * BK * D_;
        const float* Vt = Vb + (size_t)kb * BK * D_;
        for (int t = tid; t < 128 * 32; t += 512) {
            const int r = t >> 5, c4 = (t & 31) << 2;
            const int off = (r * HSTR + c4) * 2;
            split_store(smp, KHI, KLO, off,
                        *reinterpret_cast<const float4*>(Kt + r * D_ + c4));
            split_store(smp, VHI, VLO, off,
                        *reinterpret_cast<const float4*>(Vt + r * D_ + c4));
        }
        __syncthreads();   // (b) K,V ready

        // ---- S = Q K^T over this warp's 64 keys: sacc[8][4] ----
        float sacc[8][4];
#pragma unroll
        for (int nt = 0; nt < 8; nt++)
#pragma unroll
            for (int j = 0; j < 4; j++) sacc[nt][j] = 0.0f;

#pragma unroll
        for (int ks = 0; ks < 8; ks++) {
            uint ah[4], al[4];
            ldsm4(ah, sb + QHI + aoff + ks * 32);
            ldsm4(al, sb + QLO + aoff + ks * 32);
#pragma unroll
            for (int nt2 = 0; nt2 < 4; nt2++) {
                uint bh[4], bl[4];
                const uint kbo = boff + (uint)(nt2 * 16 * HSTR * 2 + ks * 32);
                ldsm4(bh, sb + KHI + kbo);
                ldsm4(bl, sb + KLO + kbo);
                mma16816(sacc[2 * nt2],     ah, bh[0], bh[1]);
                mma16816(sacc[2 * nt2],     al, bh[0], bh[1]);
                mma16816(sacc[2 * nt2],     ah, bl[0], bl[1]);
                mma16816(sacc[2 * nt2 + 1], ah, bh[2], bh[3]);
                mma16816(sacc[2 * nt2 + 1], al, bh[2], bh[3]);
                mma16816(sacc[2 * nt2 + 1], ah, bl[2], bl[3]);
            }
        }

        // ---- scale + half-local max ----
        float mx0 = -1e30f, mx1 = -1e30f;
#pragma unroll
        for (int nt = 0; nt < 8; nt++) {
            sacc[nt][0] *= rsc0; sacc[nt][1] *= rsc0;
            sacc[nt][2] *= rsc1; sacc[nt][3] *= rsc1;
            mx0 = fmaxf(mx0, fmaxf(sacc[nt][0], sacc[nt][1]));
            mx1 = fmaxf(mx1, fmaxf(sacc[nt][2], sacc[nt][3]));
        }
        mx0 = fmaxf(mx0, __shfl_xor_sync(0xffffffffu, mx0, 1));
        mx0 = fmaxf(mx0, __shfl_xor_sync(0xffffffffu, mx0, 2));
        mx1 = fmaxf(mx1, __shfl_xor_sync(0xffffffffu, mx1, 1));
        mx1 = fmaxf(mx1, __shfl_xor_sync(0xffffffffu, mx1, 2));

        if (tc == 0) {
            redM[h * 128 + qr + g]     = mx0;
            redM[h * 128 + qr + g + 8] = mx1;
        }
        __syncthreads();   // (c) max exchange; also: all QK reads of K done
        mx0 = fmaxf(mx0, redM[(1 - h) * 128 + qr + g]);
        mx1 = fmaxf(mx1, redM[(1 - h) * 128 + qr + g + 8]);

        const float mn0 = fmaxf(m0, mx0), mn1 = fmaxf(m1, mx1);
        const float al0 = __expf(m0 - mn0), al1 = __expf(m1 - mn1);
        m0 = mn0; m1 = mn1;

        // ---- exp + Z partial ----
        float zp0 = 0.0f, zp1 = 0.0f;
#pragma unroll
        for (int nt = 0; nt < 8; nt++) {
            sacc[nt][0] = __expf(sacc[nt][0] - mn0); zp0 += sacc[nt][0];
            sacc[nt][1] = __expf(sacc[nt][1] - mn0); zp0 += sacc[nt][1];
            sacc[nt][2] = __expf(sacc[nt][2] - mn1); zp1 += sacc[nt][2];
            sacc[nt][3] = __expf(sacc[nt][3] - mn1); zp1 += sacc[nt][3];
        }
        zp0 += __shfl_xor_sync(0xffffffffu, zp0, 1);
        zp0 += __shfl_xor_sync(0xffffffffu, zp0, 2);
        zp1 += __shfl_xor_sync(0xffffffffu, zp1, 1);
        zp1 += __shfl_xor_sync(0xffffffffu, zp1, 2);
        z0 = z0 * al0 + zp0;
        z1 = z1 * al1 + zp1;

        // ---- dropout ----
        uint w0[2], w1[2];
#pragma unroll
        for (int j = 0; j < 2; j++) {
            w0[j] = g_mask[rowb0 + (unsigned)(kb * 4 + h * 2 + j)];
            w1[j] = g_mask[rowb1 + (unsigned)(kb * 4 + h * 2 + j)];
        }
#pragma unroll
        for (int nt = 0; nt < 8; nt++) {
            const uint bit = (uint)((nt & 3) * 8 + tc * 2);
            const uint ww0 = w0[nt >> 2], ww1 = w1[nt >> 2];
            if (!((ww0 >> bit) & 1u))        sacc[nt][0] = 0.0f;
            if (!((ww0 >> (bit + 1)) & 1u))  sacc[nt][1] = 0.0f;
            if (!((ww1 >> bit) & 1u))        sacc[nt][2] = 0.0f;
            if (!((ww1 >> (bit + 1)) & 1u))  sacc[nt][3] = 0.0f;
        }

        // ---- write P (hi/lo) into K planes; rescale O partial ----
#pragma unroll
        for (int nt = 0; nt < 8; nt++) {
            const int keyc = h * 64 + (nt >> 1) * 16 + (nt & 1) * 8 + tc * 2;
            const float s0 = sacc[nt][0], s1 = sacc[nt][1];
            const float s2 = sacc[nt][2], s3 = sacc[nt][3];
            const float h0 = hif(s0), h1 = hif(s1), h2 = hif(s2), h3 = hif(s3);
            const int off0 = ((qr + g) * HSTR + keyc) * 2;
            const int off1 = ((qr + g + 8) * HSTR + keyc) * 2;
            *(uint*)(smp + KHI + off0) = packh2(h0, h1);
            *(uint*)(smp + KLO + off0) = packh2(s0 - h0, s1 - h1);
            *(uint*)(smp + KHI + off1) = packh2(h2, h3);
            *(uint*)(smp + KLO + off1) = packh2(s2 - h2, s3 - h3);
        }
#pragma unroll
        for (int nt = 0; nt < 8; nt++) {
            oacc[nt][0] *= al0; oacc[nt][1] *= al0;
            oacc[nt][2] *= al1; oacc[nt][3] *= al1;
        }
        __syncthreads();   // (d) P ready

        // ---- O_partial += P V over all 128 keys, this warp's 64 d-cols ----
#pragma unroll
        for (int ks = 0; ks < 8; ks++) {
            uint ph[4], pl[4];
            ldsm4(ph, sb + KHI + aoff + ks * 32);
            ldsm4(pl, sb + KLO + aoff + ks * 32);
#pragma unroll
            for (int dt2 = 0; dt2 < 4; dt2++) {
                uint vh[4], vl[4];
                const uint vbo = voff + (uint)(ks * 16 * HSTR * 2 + dt2 * 32);
                ldsm4t(vh, sb + VHI + vbo);
                ldsm4t(vl, sb + VLO + vbo);
                mma16816(oacc[2 * dt2],     ph, vh[0], vh[1]);
                mma16816(oacc[2 * dt2],     pl, vh[0], vh[1]);
                mma16816(oacc[2 * dt2],     ph, vl[0], vl[1]);
                mma16816(oacc[2 * dt2 + 1], ph, vh[2], vh[3]);
                mma16816(oacc[2 * dt2 + 1], pl, vh[2], vh[3]);
                mma16816(oacc[2 * dt2 + 1], ph, vl[2], vl[3]);
            }
        }
    }

    // ---- epilogue: exchange Z halves, normalize, store ----
    if (tc == 0) {
        redZ[h * 128 + qr + g]     = z0;
        redZ[h * 128 + qr + g + 8] = z1;
    }
    __syncthreads();
    const float Z0 = redZ[qr + g]     + redZ[128 + qr + g];
    const float Z1 = redZ[qr + g + 8] + redZ[128 + qr + g + 8];
    const float inv0 = 1.0f / (Z0 * kp);
    const float inv1 = 1.0f / (Z1 * kp);

    float* o0 = Out + (size_t)(b * S_ + qbase + qr + g) * D_ + h * 64 + tc * 2;
    float* o1 = Out + (size_t)(b * S_ + qbase + qr + g + 8) * D_ + h * 64 + tc * 2;
#pragma unroll
    for (int nt = 0; nt < 8; nt++) {
        const int dcol = (nt >> 1) * 16 + (nt & 1) * 8;
        *reinterpret_cast<float2*>(o0 + dcol) =
            make_float2(oacc[nt][0] * inv0, oacc[nt][1] * inv0);
        *reinterpret_cast<float2*>(o1 + dcol) =
            make_float2(oacc[nt][2] * inv1, oacc[nt][3] * inv1);
    }
}

// ---------------------------------------------------------------------------
// Launch
// ---------------------------------------------------------------------------
extern "C" void kernel_launch(void* const* d_in, const int* in_sizes, int n_in,
                              void* d_out, int out_size) {
    const float* Q   = (const float*)d_in[0];
    const float* K   = (const float*)d_in[1];
    const float* V   = (const float*)d_in[2];
    const float* isf = (const float*)d_in[3];
    const float* dp  = (const float*)d_in[4];
    float* Out = (float*)d_out;

    cudaFuncSetAttribute(attn_kernel,
                         cudaFuncAttributeMaxDynamicSharedMemorySize, SMEM_BYTES);

    mask_kernel<<<(1u << 26) / 256, 256>>>(dp);

    dim3 grid(S_ / BQ, B_);
    attn_kernel<<<grid, 512, SMEM_BYTES>>>(Q, K, V, isf, dp, Out);
}